// round 16
// baseline (speedup 1.0000x reference)
#include <cuda_runtime.h>
#include <cuda_bf16.h>

// PSAvgPooling: B=8, H=W=64, C=1152 (= 9 bins * 128), N=512 boxes/image,
// 3x3 bins x 3x3 crop samples, bilinear gather, weighted bin-average.
//
// R15: INVERTED (image-centric scatter) decomposition.
// Gather-style kernels are pinned at 41-44us = 490MB box-private L2 traffic
// at the ~11.3TB/s LTS cap; box-level locality sorts cannot fix this (same-bin
// sharing needs near-identical box size+position -> too rare).
// Here each block owns an image tile (image, bin, row-pair, channel-half),
// loads it to smem ONCE (image crosses L2 exactly once = 151MB), and scatters
// weighted contributions of all intersecting boxes via atomicAdd.
//   kernel 1: zero out + list counters (out is accumulated, graph-replayed)
//   kernel 2: bucket boxes into (img,bin,rowpair) lists
//   kernel 3: tile load + separable-weight scatter (R8-proven merge math)

namespace {

constexpr int Hh   = 64;
constexpr int Ww   = 64;
constexpr int Cc   = 1152;   // total channels
constexpr int Csz  = 128;    // channels per bin
constexpr int NRP  = 32;     // row-pairs per image
constexpr int MAXB = 16;     // max images supported by scratch
constexpr int NLIST = MAXB * 9 * NRP;       // 4608 lists
constexpr int LCAP  = 512;                  // max boxes per list (<= boxes/image)

__device__ int g_cnt[NLIST];
__device__ int g_list[NLIST * LCAP];

// Merged per-axis (index, weight) list for one (box, bin, axis). R8-proven.
__device__ __forceinline__ int axis_merge(float lo0, float hi0, int bidx, int limi,
                                          int* lr, float* lw) {
    const float step = (hi0 - lo0) * (1.0f / 3.0f);
    const float lim  = (float)limi;
    int n = 0, M = -100;
    #pragma unroll
    for (int p = 0; p < 3; p++) {
        const float c = (lo0 + ((float)bidx + 0.5f * (float)p) * step) * lim;
        const float f = floorf(c);
        const float w = c - f;
        const int   fi  = (int)f;
        const int   loI = min(max(fi,     0), limi);
        const int   hiI = min(max(fi + 1, 0), limi);
        const float m   = (c >= 0.0f && c <= lim) ? 1.0f : 0.0f;
        const float wlo = (1.0f - w) * m;
        const float whi = w * m;
        const int i1 = max(n - 1, 0);
        const int i2 = max(n - 2, 0);
        if (loI > M) {
            lr[n] = loI; lw[n] = wlo; n++;
            if (hiI > loI) { lr[n] = hiI; lw[n] = whi; n++; }
            else           { lw[n - 1] += whi; }
        } else if (loI == M) {
            lw[i1] += wlo;
            if (hiI > M) { lr[n] = hiI; lw[n] = whi; n++; }
            else         { lw[n - 1] += whi; }
        } else {
            lw[i2] += wlo;
            lw[i1] += whi;
        }
        M = max(M, hiI);
    }
    return n;
}

__global__ __launch_bounds__(256) void zero_kernel(float* __restrict__ out, int n) {
    const int i = blockIdx.x * 256 + threadIdx.x;
    if (i < n) out[i] = 0.0f;
    if (i < NLIST) g_cnt[i] = 0;
}

__global__ __launch_bounds__(256) void build_lists_kernel(
    const float* __restrict__ boxes, int total, int nPerImage)
{
    const int t = blockIdx.x * 256 + threadIdx.x;
    if (t >= total * 9) return;
    const int box = t / 9;
    const int bin = t % 9;
    const int img = box / nPerImage;
    if (img >= MAXB) return;
    const float* bx = boxes + (size_t)box * 4;
    int lr[6]; float lw[6];
    const int n = axis_merge(bx[0], bx[2], bin / 3, Hh - 1, lr, lw);
    const int rp0 = lr[0] >> 1;
    const int rp1 = lr[n - 1] >> 1;
    for (int rp = rp0; rp <= rp1; rp++) {
        const int li  = (img * 9 + bin) * NRP + rp;
        const int pos = atomicAdd(&g_cnt[li], 1);
        if (pos < LCAP) g_list[li * LCAP + pos] = box;
    }
}

// Block = (list, channel-half). Tile: 2 rows x 64 cols x 64 ch = 32KB smem.
__global__ __launch_bounds__(256) void ps_main_kernel(
    const float* __restrict__ img,
    const float* __restrict__ boxes,
    const float* __restrict__ wts,
    float* __restrict__ out,
    int nPerImage)
{
    __shared__ float2 s_tile[128 * 32];   // [cell = r2*64+col][lane -> 2 ch]

    const int bid  = blockIdx.x;
    const int half = bid & 1;
    const int li   = bid >> 1;
    const int cnt  = min(g_cnt[li], LCAP);
    if (cnt == 0) return;

    const int rp  = li & (NRP - 1);
    const int bin = (li / NRP) % 9;
    const int im  = li / (NRP * 9);
    const int tid = threadIdx.x, lane = tid & 31, warp = tid >> 5;

    // ---- load tile: rows 2rp..2rp+1, all 64 cols, 64 channels of this half ----
    const float* ibase = img + ((size_t)im * (Hh * Ww) + (size_t)(rp * 2) * Ww) * Cc
                             + bin * Csz + half * 64;
    float4* s4 = reinterpret_cast<float4*>(s_tile);
    #pragma unroll 4
    for (int j = tid; j < 2048; j += 256) {
        const int cell = j >> 4;           // 16 float4 (64 ch) per cell
        const int c4   = j & 15;
        s4[j] = __ldg(reinterpret_cast<const float4*>(ibase + (size_t)cell * Cc) + c4);
    }
    __syncthreads();

    const float wb = wts[bin] * (1.0f / 81.0f);

    // ---- scatter: each warp takes boxes i = warp, warp+8, ... ----
    for (int i = warp; i < cnt; i += 8) {
        const int box = g_list[li * LCAP + i];
        const float* bx = boxes + (size_t)box * 4;
        int lr[6]; float lw[6]; int cr[6]; float cw[6];
        const int nR = axis_merge(bx[0], bx[2], bin / 3, Hh - 1, lr, lw);
        const int nC = axis_merge(bx[1], bx[3], bin % 3, Ww - 1, cr, cw);

        // weights of the (<=2) merged rows that fall in this row-pair
        float ry0 = 0.f, ry1 = 0.f;
        for (int k = 0; k < nR; k++) {
            if ((lr[k] >> 1) == rp) {
                if (lr[k] & 1) ry1 += lw[k]; else ry0 += lw[k];
            }
        }
        if (ry0 == 0.f && ry1 == 0.f) continue;   // uniform per warp
        ry0 *= wb; ry1 *= wb;

        float a0 = 0.f, a1 = 0.f;
        for (int j2 = 0; j2 < nC; j2++) {
            const int col = cr[j2];
            const float w0 = ry0 * cw[j2];
            const float w1 = ry1 * cw[j2];
            const float2 v0 = s_tile[col * 32 + lane];          // row 2rp
            const float2 v1 = s_tile[(64 + col) * 32 + lane];   // row 2rp+1
            a0 += w0 * v0.x + w1 * v1.x;
            a1 += w0 * v0.y + w1 * v1.y;
        }

        float* o = out + (size_t)box * Csz + half * 64 + lane * 2;
        atomicAdd(o,     a0);
        atomicAdd(o + 1, a1);
    }
}

} // namespace

extern "C" void kernel_launch(void* const* d_in, const int* in_sizes, int n_in,
                              void* d_out, int out_size) {
    const float* img   = (const float*)d_in[0];  // [B,64,64,1152] fp32
    const float* boxes = (const float*)d_in[1];  // [B,N,4] fp32
    const float* wts   = (const float*)d_in[2];  // [9] fp32
    float* out = (float*)d_out;                  // [B*N, 128] fp32

    const int B          = in_sizes[0] / (Hh * Ww * Cc);
    const int totalBoxes = in_sizes[1] / 4;
    const int nPerImage  = totalBoxes / B;
    const int Bc         = min(B, MAXB);

    zero_kernel<<<(out_size + 255) / 256, 256>>>(out, out_size);
    build_lists_kernel<<<(totalBoxes * 9 + 255) / 256, 256>>>(boxes, totalBoxes, nPerImage);
    ps_main_kernel<<<Bc * 9 * NRP * 2, 256>>>(img, boxes, wts, out, nPerImage);
}

// round 17
// speedup vs baseline: 4.5242x; 4.5242x over previous
#include <cuda_runtime.h>
#include <cuda_bf16.h>

// PSAvgPooling: B=8, H=W=64, C=1152 (= 9 bins * 128), N=512 boxes/image,
// 3x3 bins x 3x3 crop samples, bilinear gather, weighted bin-average.
//
// R16: R2d (proven 41.4us shape) + occupancy unlock.
// Profile of all 41us gather kernels: L1~62%, L2~62%, issue~45%, occ~46% --
// NOTHING saturated => latency x parallelism bound. R2d was register-capped
// (64 regs x 128thr x 8 blocks = full 64k reg file = 32-warp ceiling).
// __launch_bounds__(128, 10) caps regs at 48 -> 40 warps/SM (+38% concurrency)
// on a byte-identical inner loop.

namespace {

constexpr int Hh    = 64;
constexpr int Ww    = 64;
constexpr int Cc    = 1152;   // total channels
constexpr int Csz   = 128;    // channels per bin (Cc / 9)
constexpr int NB    = 3;      // bins per dim
constexpr int NSAMP = 81;     // 9 bins * 9 crop samples
constexpr int NWARP = 4;      // warps per box

__global__ __launch_bounds__(NWARP * 32, 10) void ps_pool_kernel(
    const float* __restrict__ img,    // [B, H, W, C]
    const float* __restrict__ boxes,  // [B*N, 4]  (y1,x1,y2,x2 normalized)
    const float* __restrict__ wts,    // [9]
    float* __restrict__ out,          // [B*N, 128]
    int nPerImage)
{
    __shared__ int4   s_off[NSAMP];        // BYTE offsets of 4 bilinear corners (incl. bin*128)
    __shared__ float4 s_w[NSAMP];          // bilinear weights * bin weight * inside mask
    __shared__ float4 s_red[NWARP][32];    // per-warp partial accumulators

    const int box_id = blockIdx.x;
    const int b      = box_id / nPerImage;
    const float* __restrict__ image = img + (size_t)b * (Hh * Ww * Cc);
    const float* bx = boxes + (size_t)box_id * 4;
    const int tid  = threadIdx.x;
    const int lane = tid & 31;
    const int warp = tid >> 5;

    const float y1 = bx[0], x1 = bx[1], y2 = bx[2], x2 = bx[3];
    const float step_y = (y2 - y1) * (1.0f / 3.0f);
    const float step_x = (x2 - x1) * (1.0f / 3.0f);

    // ---- Precompute 81 samples (byte offsets + fused weights), one thread each ----
    if (tid < NSAMP) {
        const int s   = tid;
        const int by  = s / 27;
        const int bxn = (s / 9) % 3;
        const int py  = (s / 3) % 3;
        const int px  = s % 3;

        // yy = (y1 + (bin + p)*step) * (H-1), p in {0, 0.5, 1}
        const float yy = (y1 + ((float)by + (float)py * 0.5f) * step_y) * (float)(Hh - 1);
        const float xx = (x1 + ((float)bxn + (float)px * 0.5f) * step_x) * (float)(Ww - 1);

        const float y0f = floorf(yy);
        const float x0f = floorf(xx);
        const float wy = yy - y0f;
        const float wx = xx - x0f;
        const int y0 = (int)y0f;
        const int x0 = (int)x0f;

        // reference clips each corner index independently
        const int y0c = min(max(y0,     0), Hh - 1);
        const int y1c = min(max(y0 + 1, 0), Hh - 1);
        const int x0c = min(max(x0,     0), Ww - 1);
        const int x1c = min(max(x0 + 1, 0), Ww - 1);

        const bool inside = (yy >= 0.0f) && (yy <= (float)(Hh - 1)) &&
                            (xx >= 0.0f) && (xx <= (float)(Ww - 1));
        const int bin = by * NB + bxn;
        const float wb = inside ? wts[bin] : 0.0f;
        const int cb = bin * Csz;

        // byte offsets (float = 4 bytes)
        s_off[s] = make_int4(((y0c * Ww + x0c) * Cc + cb) * 4,
                             ((y0c * Ww + x1c) * Cc + cb) * 4,
                             ((y1c * Ww + x0c) * Cc + cb) * 4,
                             ((y1c * Ww + x1c) * Cc + cb) * 4);
        s_w[s] = make_float4(wb * (1.0f - wy) * (1.0f - wx),
                             wb * (1.0f - wy) * wx,
                             wb * wy * (1.0f - wx),
                             wb * wy * wx);
    }
    __syncthreads();

    // ---- Each warp walks its slice of the 81 samples; lane owns 4 channels ----
    const char* __restrict__ base = (const char*)image + lane * 16;
    const int s_begin = (warp * NSAMP) / NWARP;
    const int s_end   = ((warp + 1) * NSAMP) / NWARP;

    float4 acc = make_float4(0.f, 0.f, 0.f, 0.f);

    #pragma unroll 4
    for (int s = s_begin; s < s_end; s++) {
        const int4   off = s_off[s];
        const float4 w   = s_w[s];
        const float4 v0 = __ldg((const float4*)(base + off.x));
        const float4 v1 = __ldg((const float4*)(base + off.y));
        const float4 v2 = __ldg((const float4*)(base + off.z));
        const float4 v3 = __ldg((const float4*)(base + off.w));
        acc.x += w.x * v0.x + w.y * v1.x + w.z * v2.x + w.w * v3.x;
        acc.y += w.x * v0.y + w.y * v1.y + w.z * v2.y + w.w * v3.y;
        acc.z += w.x * v0.z + w.y * v1.z + w.z * v2.z + w.w * v3.z;
        acc.w += w.x * v0.w + w.y * v1.w + w.z * v2.w + w.w * v3.w;
    }

    s_red[warp][lane] = acc;
    __syncthreads();

    // ---- First warp reduces the 4 partials and writes out ----
    if (warp == 0) {
        float4 a0 = s_red[0][lane];
        float4 a1 = s_red[1][lane];
        float4 a2 = s_red[2][lane];
        float4 a3 = s_red[3][lane];
        const float inv = 1.0f / 81.0f;  // mean over 9 samples, then /9 bins
        float4 o;
        o.x = (a0.x + a1.x + a2.x + a3.x) * inv;
        o.y = (a0.y + a1.y + a2.y + a3.y) * inv;
        o.z = (a0.z + a1.z + a2.z + a3.z) * inv;
        o.w = (a0.w + a1.w + a2.w + a3.w) * inv;
        reinterpret_cast<float4*>(out)[(size_t)box_id * (Csz / 4) + lane] = o;
    }
}

} // namespace

extern "C" void kernel_launch(void* const* d_in, const int* in_sizes, int n_in,
                              void* d_out, int out_size) {
    const float* img   = (const float*)d_in[0];  // [B,64,64,1152] fp32
    const float* boxes = (const float*)d_in[1];  // [B,N,4] fp32
    const float* wts   = (const float*)d_in[2];  // [9] fp32
    float* out = (float*)d_out;                  // [B*N, 128] fp32

    const int B          = in_sizes[0] / (Hh * Ww * Cc);
    const int totalBoxes = in_sizes[1] / 4;
    const int nPerImage  = totalBoxes / B;

    ps_pool_kernel<<<totalBoxes, NWARP * 32>>>(img, boxes, wts, out, nPerImage);
}